// round 2
// baseline (speedup 1.0000x reference)
#include <cuda_runtime.h>

// TemporalSpike: RLeaky SNN recurrence.
//   rec   = spk_prev @ W^T + b_lin          (spk binary -> mask + predicated adds)
//   mem   = 0.9*mem + x_t + rec - spk_prev  (THRESH=1, reset-subtract)
//   spk   = (mem > 1.0) ? 1 : 0
// Shapes: x (16,128,512,32); W (32,32); b_lin (32).
// Out: spikes (16,128,512,32) then mems (16,128,512,32), concatenated.

#define BB 16
#define TT 128
#define NN 512
#define FF 32
#define ROWS (BB * NN)        // 8192 independent recurrences
#define WPB 8                 // warps per block
#define TSTRIDE (NN * FF)     // 16384 floats between consecutive t

__global__ __launch_bounds__(WPB * 32)
void temporal_spike_kernel(const float* __restrict__ x,
                           const float* __restrict__ W,
                           const float* __restrict__ b_lin,
                           float* __restrict__ out)
{
    const int warp = blockIdx.x * WPB + (threadIdx.x >> 5);
    const int lane = threadIdx.x & 31;
    // ROWS = 1024 blocks * 8 warps exactly; no bounds check needed, but keep safe:
    if (warp >= ROWS) return;

    const int b = warp >> 9;      // / NN
    const int n = warp & (NN - 1);

    // Lane g holds row g of W: W[g, 0..31] (contiguous, row-major).
    float w[32];
    const float4* Wr = reinterpret_cast<const float4*>(W + lane * FF);
    #pragma unroll
    for (int i = 0; i < 8; i++) {
        float4 v = Wr[i];
        w[4*i+0] = v.x; w[4*i+1] = v.y; w[4*i+2] = v.z; w[4*i+3] = v.w;
    }
    const float bias = b_lin[lane];

    const int base = (b * TT * NN + n) * FF + lane;   // t=0 element for this lane
    const float* xp = x + base;
    float* sp = out + base;                            // spikes
    float* mp = sp + (size_t)BB * TT * NN * FF;        // mems (second half)

    float mem = 0.0f;
    float spk = 0.0f;
    unsigned mask = 0u;

    // Prefetch pipeline (x independent of recurrence), depth 4.
    float xbuf[4];
    #pragma unroll
    for (int i = 0; i < 4; i++) xbuf[i] = xp[i * TSTRIDE];

    #pragma unroll 4
    for (int t = 0; t < TT; t++) {
        const float xv = xbuf[t & 3];
        if (t + 4 < TT) xbuf[t & 3] = xp[(t + 4) * TSTRIDE];

        // rec = bias + sum over set mask bits of w[f]; 4 accumulators for ILP.
        float r0 = bias, r1 = 0.0f, r2 = 0.0f, r3 = 0.0f;
        #pragma unroll
        for (int f = 0; f < 32; f += 4) {
            if (mask & (1u << (f + 0))) r0 += w[f + 0];
            if (mask & (1u << (f + 1))) r1 += w[f + 1];
            if (mask & (1u << (f + 2))) r2 += w[f + 2];
            if (mask & (1u << (f + 3))) r3 += w[f + 3];
        }
        const float rec = (r0 + r1) + (r2 + r3);

        mem = fmaf(0.9f, mem, xv + rec - spk);   // THRESH=1 -> subtract spk directly
        const bool fire = (mem > 1.0f);
        spk = fire ? 1.0f : 0.0f;
        mask = __ballot_sync(0xffffffffu, fire);

        sp[t * TSTRIDE] = spk;
        mp[t * TSTRIDE] = mem;
    }
}

extern "C" void kernel_launch(void* const* d_in, const int* in_sizes, int n_in,
                              void* d_out, int out_size)
{
    const float* x     = (const float*)d_in[0];
    const float* W     = (const float*)d_in[1];
    const float* b_lin = (const float*)d_in[2];
    float* out = (float*)d_out;

    dim3 grid(ROWS / WPB);     // 1024
    dim3 block(WPB * 32);      // 256
    temporal_spike_kernel<<<grid, block>>>(x, W, b_lin, out);
}